// round 13
// baseline (speedup 1.0000x reference)
#include <cuda_runtime.h>
#include <cuda_fp16.h>
#include <cstdint>

#define BSZ    256
#define BOND   5
#define NDIM   128
#define ATOM   64
#define UNITS  128
#define THREADS 256

// pitches: P_ADJ in floats (LDS.64 conflict-free: P==8 mod 32);
// half pitches (LDS.32 conflict-free: P/2 == 4 mod 32 -> P == 8 mod 64)
#define P_ADJ  136   // adj fp32 [m=64][n=128] per half
#define PH_FT  136   // F^T halfs [d=64][n=128] shared
#define PH_KT  72    // K^T halfs [u=128][d=64] per half
#define PH_X1  72    // X1 halfs [m=64][d=64]  per half

// smem layout (bytes)
#define OFF_FT   0
#define SZ_FT    (ATOM * PH_FT * 2)            // 17408
#define OFF_ADJ  (OFF_FT + SZ_FT)
#define SZ_ADJ_H (64 * P_ADJ * 4)              // 34816 per half
#define OFF_KT   (OFF_ADJ + 2 * SZ_ADJ_H)      // 87040
#define SZ_KT_H  (NDIM * PH_KT * 2)            // 18432 per half
#define OFF_X1   (OFF_KT + 2 * SZ_KT_H)        // 123904
#define SZ_X1_H  (64 * PH_X1 * 2)              // 9216 per half
#define SMEM_BYTES (OFF_X1 + 2 * SZ_X1_H)      // 142336

// pack two fp32 -> half2 (first asm source -> HIGH half)
__device__ __forceinline__ uint32_t pack_h2(float lo, float hi) {
    uint32_t r;
    asm("cvt.rn.f16x2.f32 %0, %1, %2;" : "=r"(r) : "f"(hi), "f"(lo));
    return r;
}

__device__ __forceinline__ void mma_f16(float c[4], const uint32_t a[4], const uint32_t b[2]) {
    asm volatile(
        "mma.sync.aligned.m16n8k16.row.col.f32.f16.f16.f32 "
        "{%0,%1,%2,%3}, {%4,%5,%6,%7}, {%8,%9}, {%0,%1,%2,%3};"
        : "+f"(c[0]), "+f"(c[1]), "+f"(c[2]), "+f"(c[3])
        : "r"(a[0]), "r"(a[1]), "r"(a[2]), "r"(a[3]), "r"(b[0]), "r"(b[1]));
}

__device__ __forceinline__ uint32_t smem_u32(const void* p) {
    uint32_t a;
    asm("{ .reg .u64 t; cvta.to.shared.u64 t, %1; cvt.u32.u64 %0, t; }" : "=r"(a) : "l"(p));
    return a;
}
__device__ __forceinline__ void cpa16(uint32_t s, const float4* g) {
    asm volatile("cp.async.cg.shared.global [%0], [%1], 16;" :: "r"(s), "l"(g) : "memory");
}
#define CP_COMMIT() asm volatile("cp.async.commit_group;" ::: "memory")
template<int N> __device__ __forceinline__ void cp_wait() {
    asm volatile("cp.async.wait_group %0;" :: "n"(N) : "memory");
}
__device__ __forceinline__ void hbar(int h) {
    asm volatile("bar.sync %0, 128;" :: "r"(h + 1) : "memory");
}

__device__ __forceinline__ float sel4(float a0, float a1, float a2, float a3, int idx) {
    float x = (idx & 1) ? a1 : a0;
    float y = (idx & 1) ? a3 : a2;
    return (idx & 2) ? y : x;
}
// 4x4 transpose in 4-lane group: lane p holds M[row0+p][c0..c0+3] -> bb[j]=M[row0+j][c0+p]
__device__ __forceinline__ void xpose4(float4 v, int p, float bb[4]) {
    float r0 = sel4(v.x, v.y, v.z, v.w, p ^ 0);
    float r1 = __shfl_xor_sync(0xffffffffu, sel4(v.x, v.y, v.z, v.w, p ^ 1), 1);
    float r2 = __shfl_xor_sync(0xffffffffu, sel4(v.x, v.y, v.z, v.w, p ^ 2), 2);
    float r3 = __shfl_xor_sync(0xffffffffu, sel4(v.x, v.y, v.z, v.w, p ^ 3), 3);
    bb[0] = sel4(r0, r1, r2, r3, p ^ 0);
    bb[1] = sel4(r0, r1, r2, r3, p ^ 1);
    bb[2] = sel4(r0, r1, r2, r3, p ^ 2);
    bb[3] = sel4(r0, r1, r2, r3, p ^ 3);
}

__global__ void __launch_bounds__(THREADS, 1)
rgc_kernel(const float* __restrict__ adjacency,
           const float* __restrict__ features,
           const float* __restrict__ kern,
           float* __restrict__ out) {
    extern __shared__ char smc[];
    const int tid = threadIdx.x;
    const int h   = tid >> 7;          // half (warps 0-3 | 4-7)
    const int ht  = tid & 127;
    const int lw  = ht >> 5;           // local warp 0-3
    const int wid = tid >> 5;
    const int lid = tid & 31;
    const int r4  = lid >> 2;
    const int c4  = lid & 3;
    const int b   = blockIdx.x;
    const int mh  = h << 6;

    __half* sFT  = reinterpret_cast<__half*>(smc + OFF_FT);
    float*  sAdj = reinterpret_cast<float*>(smc + OFF_ADJ + h * SZ_ADJ_H);
    __half* sKT  = reinterpret_cast<__half*>(smc + OFF_KT + h * SZ_KT_H);
    __half* sX1  = reinterpret_cast<__half*>(smc + OFF_X1 + h * SZ_X1_H);
    const uint32_t sAdjB = smem_u32(sAdj);

    // per-half warp tiling (champion shapes): G1 32m x 32d, G2 32m x 64u
    const int m0 = (lw & 1) * 32;
    const int d0 = (lw >> 1) * 32;
    const int u0 = (lw >> 1) * 64;

    const float4* adjB  = reinterpret_cast<const float4*>(adjacency) + (size_t)(b * BOND) * 4096;
    const float4* kerB  = reinterpret_cast<const float4*>(kern)      + (size_t)(b * BOND) * 2048;
    const float4* featB = reinterpret_cast<const float4*>(features)  + (size_t)b * 2048;

    auto stage_adj_chunk = [&](int e, int c) {
        const float4* src = adjB + (size_t)e * 4096;
        #pragma unroll
        for (int t = 0; t < 4; t++) {
            int i = ht + t * 128;               // 0..511
            int m = i >> 3, j = i & 7;
            cpa16(sAdjB + (uint32_t)(m * P_ADJ + (c * 8 + j) * 4) * 4u,
                  src + (mh + m) * 32 + c * 8 + j);
        }
    };
    auto commit_adj = [&](int e) {
        stage_adj_chunk(e, 0); CP_COMMIT();
        stage_adj_chunk(e, 1); CP_COMMIT();
        stage_adj_chunk(e, 2); CP_COMMIT();
        stage_adj_chunk(e, 3); CP_COMMIT();
    };

    // ---- prologue: F^T as fp16 (LDG + shuffle transpose + packed STS) ----
    {
        #pragma unroll
        for (int it = 0; it < 4; it++) {
            int n0 = 4 * (wid + 8 * it);        // n-quad base
            float4 v0 = featB[(n0 + c4) * 16 + r4];
            float4 v1 = featB[(n0 + c4) * 16 + r4 + 8];
            float b0[4], b1[4];
            xpose4(v0, c4, b0);                 // b0[j] = F[n0+j][4*r4+c4]
            xpose4(v1, c4, b1);                 // b1[j] = F[n0+j][32+4*r4+c4]
            int da = 4 * r4 + c4;
            int db = 32 + 4 * r4 + c4;
            uint2 w0 = make_uint2(pack_h2(b0[0], b0[1]), pack_h2(b0[2], b0[3]));
            uint2 w1 = make_uint2(pack_h2(b1[0], b1[1]), pack_h2(b1[2], b1[3]));
            *reinterpret_cast<uint2*>(sFT + da * PH_FT + n0) = w0;
            *reinterpret_cast<uint2*>(sFT + db * PH_FT + n0) = w1;
        }
        __syncthreads();                        // F^T visible to both halves
        commit_adj(0);
    }

    float acc2[2][8][4];
    #pragma unroll
    for (int mt = 0; mt < 2; mt++)
        #pragma unroll
        for (int nt = 0; nt < 8; nt++)
            #pragma unroll
            for (int k = 0; k < 4; k++) acc2[mt][nt][k] = 0.0f;

    float acc1[2][4][4];

    // G1 one k16 step (n-dim k): s = 0..7
    auto g1_step = [&](int s) {
        const int k0 = s * 16;
        uint32_t a[2][4], bf[4][2];
        #pragma unroll
        for (int mt = 0; mt < 2; mt++) {
            const float* pa = sAdj + (m0 + mt * 16 + r4) * P_ADJ + k0 + 2 * c4;
            float2 p0 = *reinterpret_cast<const float2*>(pa);
            float2 q0 = *reinterpret_cast<const float2*>(pa + 8 * P_ADJ);
            float2 p1 = *reinterpret_cast<const float2*>(pa + 8);
            float2 q1 = *reinterpret_cast<const float2*>(pa + 8 * P_ADJ + 8);
            a[mt][0] = pack_h2(p0.x, p0.y);     // row g,   k-lo pair
            a[mt][1] = pack_h2(q0.x, q0.y);     // row g+8, k-lo
            a[mt][2] = pack_h2(p1.x, p1.y);     // row g,   k-hi
            a[mt][3] = pack_h2(q1.x, q1.y);     // row g+8, k-hi
        }
        #pragma unroll
        for (int nt = 0; nt < 4; nt++) {
            const __half* pb = sFT + (d0 + nt * 8 + r4) * PH_FT + k0 + 2 * c4;
            bf[nt][0] = *reinterpret_cast<const uint32_t*>(pb);
            bf[nt][1] = *reinterpret_cast<const uint32_t*>(pb + 8);
        }
        #pragma unroll
        for (int mt = 0; mt < 2; mt++)
            #pragma unroll
            for (int nt = 0; nt < 4; nt++)
                mma_f16(acc1[mt][nt], a[mt], bf[nt]);
    };

    // K^T batches: item i: LDG K[4i+c4][u-f4 = lw*8+r4]; consume -> KT[u][4i..4i+3]
    const int ukf4 = lw * 8 + r4;               // fixed u-float4 column per thread
    float4 kbufA[8], kbufB[8];
    auto ldg_kA = [&](int e) {
        const float4* src = kerB + (size_t)e * 2048;
        #pragma unroll
        for (int i = 0; i < 8; i++) kbufA[i] = src[(4 * i + c4) * 32 + ukf4];
    };
    auto ldg_kB = [&](int e) {
        const float4* src = kerB + (size_t)e * 2048;
        #pragma unroll
        for (int i = 0; i < 8; i++) kbufB[i] = src[(4 * (i + 8) + c4) * 32 + ukf4];
    };
    auto consume_k = [&](float4* buf, int ibase) {
        const int u = ukf4 * 4 + c4;
        #pragma unroll
        for (int i = 0; i < 8; i++) {
            float bb[4];
            xpose4(buf[i], c4, bb);             // bb[j] = K[4*(ibase+i)+j][u]
            uint2 w = make_uint2(pack_h2(bb[0], bb[1]), pack_h2(bb[2], bb[3]));
            *reinterpret_cast<uint2*>(sKT + u * PH_KT + 4 * (ibase + i)) = w;
        }
    };

    // G2 one k16 step (d-dim k): s = 0..3
    auto g2_step = [&](int s) {
        const int k0 = s * 16;
        uint32_t a[2][4], bf[8][2];
        #pragma unroll
        for (int mt = 0; mt < 2; mt++) {
            const __half* pa = sX1 + (m0 + mt * 16 + r4) * PH_X1 + k0 + 2 * c4;
            a[mt][0] = *reinterpret_cast<const uint32_t*>(pa);
            a[mt][1] = *reinterpret_cast<const uint32_t*>(pa + 8 * PH_X1);
            a[mt][2] = *reinterpret_cast<const uint32_t*>(pa + 8);
            a[mt][3] = *reinterpret_cast<const uint32_t*>(pa + 8 * PH_X1 + 8);
        }
        #pragma unroll
        for (int nt = 0; nt < 8; nt++) {
            const __half* pb = sKT + (u0 + nt * 8 + r4) * PH_KT + k0 + 2 * c4;
            bf[nt][0] = *reinterpret_cast<const uint32_t*>(pb);
            bf[nt][1] = *reinterpret_cast<const uint32_t*>(pb + 8);
        }
        #pragma unroll
        for (int mt = 0; mt < 2; mt++)
            #pragma unroll
            for (int nt = 0; nt < 8; nt++)
                mma_f16(acc2[mt][nt], a[mt], bf[nt]);
    };

    // Bond loop. FIFO: entry = {C0..C3}; s-ladder wait<3,2,1,0>; K via LDG batches.
    #pragma unroll 1
    for (int e = 0; e < BOND; e++) {
        #pragma unroll
        for (int mt = 0; mt < 2; mt++)
            #pragma unroll
            for (int nt = 0; nt < 4; nt++)
                #pragma unroll
                for (int k = 0; k < 4; k++) acc1[mt][nt][k] = 0.0f;

        cp_wait<3>(); hbar(h);                  // C0 ready; prev G2 closed
        g1_step(0); g1_step(1);
        cp_wait<2>(); hbar(h);
        ldg_kA(e);                              // K batch A in flight over 2 chunks
        g1_step(2); g1_step(3);
        cp_wait<1>(); hbar(h);
        ldg_kB(e);
        g1_step(4); g1_step(5);
        cp_wait<0>(); hbar(h);
        g1_step(6); g1_step(7);

        consume_k(kbufA, 0);                    // K^T halfs -> smem
        consume_k(kbufB, 8);

        // X1 -> fp16 smem (C-fragment pairs are k-adjacent: direct half2 pack)
        #pragma unroll
        for (int mt = 0; mt < 2; mt++) {
            #pragma unroll
            for (int nt = 0; nt < 4; nt++) {
                const int row = m0 + mt * 16 + r4;
                const int col = d0 + nt * 8 + 2 * c4;
                *reinterpret_cast<uint32_t*>(sX1 + row * PH_X1 + col) =
                    pack_h2(acc1[mt][nt][0], acc1[mt][nt][1]);
                *reinterpret_cast<uint32_t*>(sX1 + (row + 8) * PH_X1 + col) =
                    pack_h2(acc1[mt][nt][2], acc1[mt][nt][3]);
            }
        }
        hbar(h);                                // X1 + K^T visible; adj(e) dead
        if (e + 1 < BOND) commit_adj(e + 1);    // flies during G2

        g2_step(0); g2_step(1); g2_step(2); g2_step(3);
        // next bond's first hbar closes G2 before smem reuse
    }

    // ---- epilogue: ReLU + store OUT[b][mh+m][u] ----
    float* ob = out + (size_t)b * (NDIM * UNITS) + (size_t)mh * UNITS;
    #pragma unroll
    for (int mt = 0; mt < 2; mt++) {
        #pragma unroll
        for (int nt = 0; nt < 8; nt++) {
            const int row = m0 + mt * 16 + r4;
            const int col = u0 + nt * 8 + 2 * c4;
            float2 v0 = make_float2(fmaxf(acc2[mt][nt][0], 0.0f), fmaxf(acc2[mt][nt][1], 0.0f));
            float2 v1 = make_float2(fmaxf(acc2[mt][nt][2], 0.0f), fmaxf(acc2[mt][nt][3], 0.0f));
            *reinterpret_cast<float2*>(ob + row * UNITS + col)       = v0;
            *reinterpret_cast<float2*>(ob + (row + 8) * UNITS + col) = v1;
        }
    }
}

extern "C" void kernel_launch(void* const* d_in, const int* in_sizes, int n_in,
                              void* d_out, int out_size) {
    const float* adj  = nullptr;
    const float* feat = nullptr;
    const float* ker  = nullptr;
    for (int i = 0; i < n_in; i++) {
        if      (in_sizes[i] == BSZ * BOND * NDIM * NDIM)  adj  = (const float*)d_in[i];
        else if (in_sizes[i] == BSZ * NDIM * ATOM)         feat = (const float*)d_in[i];
        else if (in_sizes[i] == BSZ * BOND * ATOM * UNITS) ker  = (const float*)d_in[i];
    }
    if (!adj)  adj  = (const float*)d_in[0];
    if (!feat) feat = (const float*)d_in[1];
    if (!ker)  ker  = (const float*)d_in[2];

    cudaFuncSetAttribute(rgc_kernel, cudaFuncAttributeMaxDynamicSharedMemorySize, SMEM_BYTES);
    rgc_kernel<<<BSZ, THREADS, SMEM_BYTES>>>(adj, feat, ker, (float*)d_out);
}

// round 14
// speedup vs baseline: 1.3704x; 1.3704x over previous
#include <cuda_runtime.h>
#include <cuda_fp16.h>
#include <cstdint>

#define BSZ    256
#define BOND   5
#define NDIM   128
#define ATOM   64
#define UNITS  128
#define THREADS 256

// pitches. P_ADJ (fp32 words): LDS.64 @ stride-2c4 conflict-free (P==8 mod 32).
// P_K (fp32 words): scalar LDS.32 @ k-row 2c4 -> need 2*P_K==8 mod 32 -> P_K==4 mod 16.
// half pitches: LDS.32 conflict-free (P==8 mod 64).
#define P_ADJ  136   // adj fp32 [m=64][n=128] per half
#define P_K    132   // K   fp32 [d=64][u=128] per half
#define PH_FT  136   // F^T fp16 [d=64][n=128] shared
#define PH_X1  72    // X1  fp16 [m=64][d=64]  per half

// smem layout (bytes)
#define OFF_FT   0
#define SZ_FT    (ATOM * PH_FT * 2)            // 17408
#define OFF_ADJ  (OFF_FT + SZ_FT)
#define SZ_ADJ_H (64 * P_ADJ * 4)              // 34816 per half
#define OFF_K    (OFF_ADJ + 2 * SZ_ADJ_H)      // 87040
#define SZ_K_H   (ATOM * P_K * 4)              // 33792 per half
#define OFF_X1   (OFF_K + 2 * SZ_K_H)          // 154624
#define SZ_X1_H  (64 * PH_X1 * 2)              // 9216 per half
#define SMEM_BYTES (OFF_X1 + 2 * SZ_X1_H)      // 173056 (< 227KB)

// pack two fp32 -> half2 (lo -> low half)
__device__ __forceinline__ uint32_t pack_h2(float lo, float hi) {
    uint32_t r;
    asm("cvt.rn.f16x2.f32 %0, %1, %2;" : "=r"(r) : "f"(hi), "f"(lo));
    return r;
}

__device__ __forceinline__ void mma_f16(float c[4], const uint32_t a[4], const uint32_t b[2]) {
    asm volatile(
        "mma.sync.aligned.m16n8k16.row.col.f32.f16.f16.f32 "
        "{%0,%1,%2,%3}, {%4,%5,%6,%7}, {%8,%9}, {%0,%1,%2,%3};"
        : "+f"(c[0]), "+f"(c[1]), "+f"(c[2]), "+f"(c[3])
        : "r"(a[0]), "r"(a[1]), "r"(a[2]), "r"(a[3]), "r"(b[0]), "r"(b[1]));
}

__device__ __forceinline__ uint32_t smem_u32(const void* p) {
    uint32_t a;
    asm("{ .reg .u64 t; cvta.to.shared.u64 t, %1; cvt.u32.u64 %0, t; }" : "=r"(a) : "l"(p));
    return a;
}
__device__ __forceinline__ void cpa16(uint32_t s, const float4* g) {
    asm volatile("cp.async.cg.shared.global [%0], [%1], 16;" :: "r"(s), "l"(g) : "memory");
}
#define CP_COMMIT() asm volatile("cp.async.commit_group;" ::: "memory")
template<int N> __device__ __forceinline__ void cp_wait() {
    asm volatile("cp.async.wait_group %0;" :: "n"(N) : "memory");
}
__device__ __forceinline__ void hbar(int h) {
    asm volatile("bar.sync %0, 128;" :: "r"(h + 1) : "memory");
}

__device__ __forceinline__ float sel4(float a0, float a1, float a2, float a3, int idx) {
    float x = (idx & 1) ? a1 : a0;
    float y = (idx & 1) ? a3 : a2;
    return (idx & 2) ? y : x;
}
// 4x4 transpose in 4-lane group: lane p holds M[row0+p][c0..c0+3] -> bb[j]=M[row0+j][c0+p]
__device__ __forceinline__ void xpose4(float4 v, int p, float bb[4]) {
    float r0 = sel4(v.x, v.y, v.z, v.w, p ^ 0);
    float r1 = __shfl_xor_sync(0xffffffffu, sel4(v.x, v.y, v.z, v.w, p ^ 1), 1);
    float r2 = __shfl_xor_sync(0xffffffffu, sel4(v.x, v.y, v.z, v.w, p ^ 2), 2);
    float r3 = __shfl_xor_sync(0xffffffffu, sel4(v.x, v.y, v.z, v.w, p ^ 3), 3);
    bb[0] = sel4(r0, r1, r2, r3, p ^ 0);
    bb[1] = sel4(r0, r1, r2, r3, p ^ 1);
    bb[2] = sel4(r0, r1, r2, r3, p ^ 2);
    bb[3] = sel4(r0, r1, r2, r3, p ^ 3);
}

__global__ void __launch_bounds__(THREADS, 1)
rgc_kernel(const float* __restrict__ adjacency,
           const float* __restrict__ features,
           const float* __restrict__ kern,
           float* __restrict__ out) {
    extern __shared__ char smc[];
    const int tid = threadIdx.x;
    const int h   = tid >> 7;          // half (warps 0-3 | 4-7)
    const int ht  = tid & 127;
    const int lw  = ht >> 5;           // local warp 0-3
    const int wid = tid >> 5;
    const int lid = tid & 31;
    const int r4  = lid >> 2;
    const int c4  = lid & 3;
    const int b   = blockIdx.x;
    const int mh  = h << 6;

    __half* sFT  = reinterpret_cast<__half*>(smc + OFF_FT);
    float*  sAdj = reinterpret_cast<float*>(smc + OFF_ADJ + h * SZ_ADJ_H);
    float*  sK   = reinterpret_cast<float*>(smc + OFF_K   + h * SZ_K_H);
    __half* sX1  = reinterpret_cast<__half*>(smc + OFF_X1 + h * SZ_X1_H);
    const uint32_t sAdjB = smem_u32(sAdj);
    const uint32_t sKB   = smem_u32(sK);

    // per-half warp tiling (champion shapes): G1 32m x 32d, G2 32m x 64u
    const int m0 = (lw & 1) * 32;
    const int d0 = (lw >> 1) * 32;
    const int u0 = (lw >> 1) * 64;

    const float4* adjB  = reinterpret_cast<const float4*>(adjacency) + (size_t)(b * BOND) * 4096;
    const float4* kerB  = reinterpret_cast<const float4*>(kern)      + (size_t)(b * BOND) * 2048;
    const float4* featB = reinterpret_cast<const float4*>(features)  + (size_t)b * 2048;

    auto stage_adj_chunk = [&](int e, int c) {
        const float4* src = adjB + (size_t)e * 4096;
        #pragma unroll
        for (int t = 0; t < 4; t++) {
            int i = ht + t * 128;               // 0..511
            int m = i >> 3, j = i & 7;
            cpa16(sAdjB + (uint32_t)(m * P_ADJ + (c * 8 + j) * 4) * 4u,
                  src + (mh + m) * 32 + c * 8 + j);
        }
    };
    auto commit_adj = [&](int e) {
        stage_adj_chunk(e, 0); CP_COMMIT();
        stage_adj_chunk(e, 1); CP_COMMIT();
        stage_adj_chunk(e, 2); CP_COMMIT();
        stage_adj_chunk(e, 3); CP_COMMIT();
    };
    auto stage_K = [&](int e) {                 // per-half private fp32 K copy
        const float4* src = kerB + (size_t)e * 2048;
        #pragma unroll
        for (int t = 0; t < 16; t++) {
            int i = ht + t * 128;               // 0..2047
            int dd = i >> 5, u4 = i & 31;
            cpa16(sKB + (uint32_t)(dd * P_K + u4 * 4) * 4u, src + i);
        }
    };

    // ---- prologue: F^T as fp16 (LDG + shuffle transpose + packed STS) ----
    {
        #pragma unroll
        for (int it = 0; it < 4; it++) {
            int n0 = 4 * (wid + 8 * it);        // n-quad base
            float4 v0 = featB[(n0 + c4) * 16 + r4];
            float4 v1 = featB[(n0 + c4) * 16 + r4 + 8];
            float b0[4], b1[4];
            xpose4(v0, c4, b0);                 // b0[j] = F[n0+j][4*r4+c4]
            xpose4(v1, c4, b1);                 // b1[j] = F[n0+j][32+4*r4+c4]
            int da = 4 * r4 + c4;
            int db = 32 + 4 * r4 + c4;
            uint2 w0 = make_uint2(pack_h2(b0[0], b0[1]), pack_h2(b0[2], b0[3]));
            uint2 w1 = make_uint2(pack_h2(b1[0], b1[1]), pack_h2(b1[2], b1[3]));
            *reinterpret_cast<uint2*>(sFT + da * PH_FT + n0) = w0;
            *reinterpret_cast<uint2*>(sFT + db * PH_FT + n0) = w1;
        }
        __syncthreads();                        // F^T visible to both halves
        commit_adj(0);                          // {C0},{C1},{C2},{C3}
        stage_K(0); CP_COMMIT();                // {K}
    }

    float acc2[2][8][4];
    #pragma unroll
    for (int mt = 0; mt < 2; mt++)
        #pragma unroll
        for (int nt = 0; nt < 8; nt++)
            #pragma unroll
            for (int k = 0; k < 4; k++) acc2[mt][nt][k] = 0.0f;

    float acc1[2][4][4];

    // G1 one k16 step (n-dim k): s = 0..7
    auto g1_step = [&](int s) {
        const int k0 = s * 16;
        uint32_t a[2][4], bf[4][2];
        #pragma unroll
        for (int mt = 0; mt < 2; mt++) {
            const float* pa = sAdj + (m0 + mt * 16 + r4) * P_ADJ + k0 + 2 * c4;
            float2 p0 = *reinterpret_cast<const float2*>(pa);
            float2 q0 = *reinterpret_cast<const float2*>(pa + 8 * P_ADJ);
            float2 p1 = *reinterpret_cast<const float2*>(pa + 8);
            float2 q1 = *reinterpret_cast<const float2*>(pa + 8 * P_ADJ + 8);
            a[mt][0] = pack_h2(p0.x, p0.y);     // row g,   k-lo pair
            a[mt][1] = pack_h2(q0.x, q0.y);     // row g+8, k-lo
            a[mt][2] = pack_h2(p1.x, p1.y);     // row g,   k-hi
            a[mt][3] = pack_h2(q1.x, q1.y);     // row g+8, k-hi
        }
        #pragma unroll
        for (int nt = 0; nt < 4; nt++) {
            const __half* pb = sFT + (d0 + nt * 8 + r4) * PH_FT + k0 + 2 * c4;
            bf[nt][0] = *reinterpret_cast<const uint32_t*>(pb);
            bf[nt][1] = *reinterpret_cast<const uint32_t*>(pb + 8);
        }
        #pragma unroll
        for (int mt = 0; mt < 2; mt++)
            #pragma unroll
            for (int nt = 0; nt < 4; nt++)
                mma_f16(acc1[mt][nt], a[mt], bf[nt]);
    };

    // G2 one k16 step (d-dim k): s = 0..3; B packed from fp32 K at load
    auto g2_step = [&](int s) {
        const int k0 = s * 16;
        uint32_t a[2][4], bf[8][2];
        #pragma unroll
        for (int mt = 0; mt < 2; mt++) {
            const __half* pa = sX1 + (m0 + mt * 16 + r4) * PH_X1 + k0 + 2 * c4;
            a[mt][0] = *reinterpret_cast<const uint32_t*>(pa);
            a[mt][1] = *reinterpret_cast<const uint32_t*>(pa + 8 * PH_X1);
            a[mt][2] = *reinterpret_cast<const uint32_t*>(pa + 8);
            a[mt][3] = *reinterpret_cast<const uint32_t*>(pa + 8 * PH_X1 + 8);
        }
        #pragma unroll
        for (int nt = 0; nt < 8; nt++) {
            const int u = u0 + nt * 8 + r4;
            const float* pb = sK + (k0 + 2 * c4) * P_K + u;
            bf[nt][0] = pack_h2(pb[0],         pb[P_K]);
            bf[nt][1] = pack_h2(pb[8 * P_K],   pb[9 * P_K]);
        }
        #pragma unroll
        for (int mt = 0; mt < 2; mt++)
            #pragma unroll
            for (int nt = 0; nt < 8; nt++)
                mma_f16(acc2[mt][nt], a[mt], bf[nt]);
    };

    // FIFO per half, per bond (entry flight = {C0,C1,C2,C3,K}):
    //  wait<4>|hbar| g1(0,1)   wait<3>|hbar| g1(2,3)
    //  wait<2>|hbar| g1(4,5)   wait<1>|hbar| g1(6,7)
    //  X1 store; wait<0> (K landed); hbar; commit {C0'..C3'}
    //  G2(0..3); hbar; commit {K'}
    #pragma unroll 1
    for (int e = 0; e < BOND; e++) {
        #pragma unroll
        for (int mt = 0; mt < 2; mt++)
            #pragma unroll
            for (int nt = 0; nt < 4; nt++)
                #pragma unroll
                for (int k = 0; k < 4; k++) acc1[mt][nt][k] = 0.0f;

        cp_wait<4>(); hbar(h); g1_step(0); g1_step(1);
        cp_wait<3>(); hbar(h); g1_step(2); g1_step(3);
        cp_wait<2>(); hbar(h); g1_step(4); g1_step(5);
        cp_wait<1>(); hbar(h); g1_step(6); g1_step(7);

        // X1 -> fp16 smem (C-fragment pairs are k-adjacent: direct half2 pack)
        #pragma unroll
        for (int mt = 0; mt < 2; mt++) {
            #pragma unroll
            for (int nt = 0; nt < 4; nt++) {
                const int row = m0 + mt * 16 + r4;
                const int col = d0 + nt * 8 + 2 * c4;
                *reinterpret_cast<uint32_t*>(sX1 + row * PH_X1 + col) =
                    pack_h2(acc1[mt][nt][0], acc1[mt][nt][1]);
                *reinterpret_cast<uint32_t*>(sX1 + (row + 8) * PH_X1 + col) =
                    pack_h2(acc1[mt][nt][2], acc1[mt][nt][3]);
            }
        }
        cp_wait<0>();                           // K(e) landed
        hbar(h);                                // X1 visible; adj(e) reads closed
        if (e + 1 < BOND) commit_adj(e + 1);    // flies during G2

        g2_step(0); g2_step(1); g2_step(2); g2_step(3);

        hbar(h);                                // K(e) reads closed
        if (e + 1 < BOND) { stage_K(e + 1); CP_COMMIT(); }
    }

    // ---- epilogue: ReLU + store OUT[b][mh+m][u] ----
    float* ob = out + (size_t)b * (NDIM * UNITS) + (size_t)mh * UNITS;
    #pragma unroll
    for (int mt = 0; mt < 2; mt++) {
        #pragma unroll
        for (int nt = 0; nt < 8; nt++) {
            const int row = m0 + mt * 16 + r4;
            const int col = u0 + nt * 8 + 2 * c4;
            float2 v0 = make_float2(fmaxf(acc2[mt][nt][0], 0.0f), fmaxf(acc2[mt][nt][1], 0.0f));
            float2 v1 = make_float2(fmaxf(acc2[mt][nt][2], 0.0f), fmaxf(acc2[mt][nt][3], 0.0f));
            *reinterpret_cast<float2*>(ob + row * UNITS + col)       = v0;
            *reinterpret_cast<float2*>(ob + (row + 8) * UNITS + col) = v1;
        }
    }
}

extern "C" void kernel_launch(void* const* d_in, const int* in_sizes, int n_in,
                              void* d_out, int out_size) {
    const float* adj  = nullptr;
    const float* feat = nullptr;
    const float* ker  = nullptr;
    for (int i = 0; i < n_in; i++) {
        if      (in_sizes[i] == BSZ * BOND * NDIM * NDIM)  adj  = (const float*)d_in[i];
        else if (in_sizes[i] == BSZ * NDIM * ATOM)         feat = (const float*)d_in[i];
        else if (in_sizes[i] == BSZ * BOND * ATOM * UNITS) ker  = (const float*)d_in[i];
    }
    if (!adj)  adj  = (const float*)d_in[0];
    if (!feat) feat = (const float*)d_in[1];
    if (!ker)  ker  = (const float*)d_in[2];

    cudaFuncSetAttribute(rgc_kernel, cudaFuncAttributeMaxDynamicSharedMemorySize, SMEM_BYTES);
    rgc_kernel<<<BSZ, THREADS, SMEM_BYTES>>>(adj, feat, ker, (float*)d_out);
}

// round 15
// speedup vs baseline: 1.3715x; 1.0008x over previous
#include <cuda_runtime.h>
#include <cuda_fp16.h>
#include <cstdint>

#define BSZ    256
#define BOND   5
#define NDIM   128
#define ATOM   64
#define UNITS  128
#define THREADS 256

// pitches. P_ADJ (fp32 words): LDS.64 @ stride-2c4 conflict-free (P==8 mod 32).
// P_K (fp32 words): scalar LDS.32 lanes 8c4+r4 (P==4 mod 16).
// half pitches: LDS.32 conflict-free (P==8 mod 64).
#define P_ADJ  136   // adj fp32 [m=64][n=128] per half
#define P_K    132   // K   fp32 [d=64][u=128] per half
#define PH_FT  136   // F^T fp16 [d=64][n=128] shared
#define PH_X1  72    // X1  fp16 [m=64][d=64]  per half

// smem layout (bytes)
#define OFF_FT   0
#define SZ_FT    (ATOM * PH_FT * 2)            // 17408
#define OFF_ADJ  (OFF_FT + SZ_FT)
#define SZ_ADJ_H (64 * P_ADJ * 4)              // 34816 per half
#define OFF_K    (OFF_ADJ + 2 * SZ_ADJ_H)      // 87040
#define SZ_K_H   (ATOM * P_K * 4)              // 33792 per half
#define OFF_X1   (OFF_K + 2 * SZ_K_H)          // 154624
#define SZ_X1_H  (64 * PH_X1 * 2)              // 9216 per half
#define SMEM_BYTES (OFF_X1 + 2 * SZ_X1_H)      // 173056 (< 227KB)

// pack two fp32 -> half2 (lo -> low half)
__device__ __forceinline__ uint32_t pack_h2(float lo, float hi) {
    uint32_t r;
    asm("cvt.rn.f16x2.f32 %0, %1, %2;" : "=r"(r) : "f"(hi), "f"(lo));
    return r;
}

__device__ __forceinline__ void mma_f16(float c[4], const uint32_t a[4], const uint32_t b[2]) {
    asm volatile(
        "mma.sync.aligned.m16n8k16.row.col.f32.f16.f16.f32 "
        "{%0,%1,%2,%3}, {%4,%5,%6,%7}, {%8,%9}, {%0,%1,%2,%3};"
        : "+f"(c[0]), "+f"(c[1]), "+f"(c[2]), "+f"(c[3])
        : "r"(a[0]), "r"(a[1]), "r"(a[2]), "r"(a[3]), "r"(b[0]), "r"(b[1]));
}

__device__ __forceinline__ uint32_t smem_u32(const void* p) {
    uint32_t a;
    asm("{ .reg .u64 t; cvta.to.shared.u64 t, %1; cvt.u32.u64 %0, t; }" : "=r"(a) : "l"(p));
    return a;
}
__device__ __forceinline__ void cpa16(uint32_t s, const float4* g) {
    asm volatile("cp.async.cg.shared.global [%0], [%1], 16;" :: "r"(s), "l"(g) : "memory");
}
#define CP_COMMIT() asm volatile("cp.async.commit_group;" ::: "memory")
template<int N> __device__ __forceinline__ void cp_wait() {
    asm volatile("cp.async.wait_group %0;" :: "n"(N) : "memory");
}
__device__ __forceinline__ void hbar(int h) {
    asm volatile("bar.sync %0, 128;" :: "r"(h + 1) : "memory");
}

__device__ __forceinline__ float sel4(float a0, float a1, float a2, float a3, int idx) {
    float x = (idx & 1) ? a1 : a0;
    float y = (idx & 1) ? a3 : a2;
    return (idx & 2) ? y : x;
}
// 4x4 transpose in 4-lane group: lane p holds M[row0+p][c0..c0+3] -> bb[j]=M[row0+j][c0+p]
__device__ __forceinline__ void xpose4(float4 v, int p, float bb[4]) {
    float r0 = sel4(v.x, v.y, v.z, v.w, p ^ 0);
    float r1 = __shfl_xor_sync(0xffffffffu, sel4(v.x, v.y, v.z, v.w, p ^ 1), 1);
    float r2 = __shfl_xor_sync(0xffffffffu, sel4(v.x, v.y, v.z, v.w, p ^ 2), 2);
    float r3 = __shfl_xor_sync(0xffffffffu, sel4(v.x, v.y, v.z, v.w, p ^ 3), 3);
    bb[0] = sel4(r0, r1, r2, r3, p ^ 0);
    bb[1] = sel4(r0, r1, r2, r3, p ^ 1);
    bb[2] = sel4(r0, r1, r2, r3, p ^ 2);
    bb[3] = sel4(r0, r1, r2, r3, p ^ 3);
}

__global__ void __launch_bounds__(THREADS, 1)
rgc_kernel(const float* __restrict__ adjacency,
           const float* __restrict__ features,
           const float* __restrict__ kern,
           float* __restrict__ out) {
    extern __shared__ char smc[];
    const int tid = threadIdx.x;
    const int h   = tid >> 7;          // half (warps 0-3 | 4-7)
    const int ht  = tid & 127;
    const int lw  = ht >> 5;           // local warp 0-3
    const int wid = tid >> 5;
    const int lid = tid & 31;
    const int r4  = lid >> 2;
    const int c4  = lid & 3;
    const int b   = blockIdx.x;
    const int mh  = h << 6;

    __half* sFT  = reinterpret_cast<__half*>(smc + OFF_FT);
    float*  sAdj = reinterpret_cast<float*>(smc + OFF_ADJ + h * SZ_ADJ_H);
    float*  sK   = reinterpret_cast<float*>(smc + OFF_K   + h * SZ_K_H);
    __half* sX1  = reinterpret_cast<__half*>(smc + OFF_X1 + h * SZ_X1_H);
    const uint32_t sAdjB = smem_u32(sAdj);
    const uint32_t sKB   = smem_u32(sK);

    // per-half warp tiling: G1 32m x 32d, G2 32m x 64u
    const int m0 = (lw & 1) * 32;
    const int d0 = (lw >> 1) * 32;
    const int u0 = (lw >> 1) * 64;

    const float4* adjB  = reinterpret_cast<const float4*>(adjacency) + (size_t)(b * BOND) * 4096;
    const float4* kerB  = reinterpret_cast<const float4*>(kern)      + (size_t)(b * BOND) * 2048;
    const float4* featB = reinterpret_cast<const float4*>(features)  + (size_t)b * 2048;

    // stage 64-col adjacency chunk c (c = 0/1): 1024 float4, 8 per thread
    auto stage_adj_chunk = [&](int e, int c) {
        const float4* src = adjB + (size_t)e * 4096;
        #pragma unroll
        for (int t = 0; t < 8; t++) {
            int i = ht + t * 128;               // 0..1023
            int m = i >> 4, j = i & 15;
            cpa16(sAdjB + (uint32_t)(m * P_ADJ + (c * 16 + j) * 4) * 4u,
                  src + (mh + m) * 32 + c * 16 + j);
        }
    };
    auto commit_adj = [&](int e) {
        stage_adj_chunk(e, 0); CP_COMMIT();
        stage_adj_chunk(e, 1); CP_COMMIT();
    };
    auto stage_K = [&](int e) {                 // per-half private fp32 K copy
        const float4* src = kerB + (size_t)e * 2048;
        #pragma unroll
        for (int t = 0; t < 16; t++) {
            int i = ht + t * 128;               // 0..2047
            int dd = i >> 5, u4 = i & 31;
            cpa16(sKB + (uint32_t)(dd * P_K + u4 * 4) * 4u, src + i);
        }
    };

    // ---- prologue: F^T as fp16 (LDG + shuffle transpose + packed STS) ----
    {
        #pragma unroll
        for (int it = 0; it < 4; it++) {
            int n0 = 4 * (wid + 8 * it);        // n-quad base
            float4 v0 = featB[(n0 + c4) * 16 + r4];
            float4 v1 = featB[(n0 + c4) * 16 + r4 + 8];
            float b0[4], b1[4];
            xpose4(v0, c4, b0);                 // b0[j] = F[n0+j][4*r4+c4]
            xpose4(v1, c4, b1);                 // b1[j] = F[n0+j][32+4*r4+c4]
            int da = 4 * r4 + c4;
            int db = 32 + 4 * r4 + c4;
            uint2 w0 = make_uint2(pack_h2(b0[0], b0[1]), pack_h2(b0[2], b0[3]));
            uint2 w1 = make_uint2(pack_h2(b1[0], b1[1]), pack_h2(b1[2], b1[3]));
            *reinterpret_cast<uint2*>(sFT + da * PH_FT + n0) = w0;
            *reinterpret_cast<uint2*>(sFT + db * PH_FT + n0) = w1;
        }
        __syncthreads();                        // F^T visible to both halves
        commit_adj(0);                          // {C0},{C1}
        stage_K(0); CP_COMMIT();                // {K}
    }

    float acc2[2][8][4];
    #pragma unroll
    for (int mt = 0; mt < 2; mt++)
        #pragma unroll
        for (int nt = 0; nt < 8; nt++)
            #pragma unroll
            for (int k = 0; k < 4; k++) acc2[mt][nt][k] = 0.0f;

    float acc1[2][4][4];

    // G1 fragment load for k16 step s (n-dim k)
    auto g1_load = [&](int s, uint32_t (&a)[2][4], uint32_t (&bf)[4][2]) {
        const int k0 = s * 16;
        #pragma unroll
        for (int mt = 0; mt < 2; mt++) {
            const float* pa = sAdj + (m0 + mt * 16 + r4) * P_ADJ + k0 + 2 * c4;
            float2 p0 = *reinterpret_cast<const float2*>(pa);
            float2 q0 = *reinterpret_cast<const float2*>(pa + 8 * P_ADJ);
            float2 p1 = *reinterpret_cast<const float2*>(pa + 8);
            float2 q1 = *reinterpret_cast<const float2*>(pa + 8 * P_ADJ + 8);
            a[mt][0] = pack_h2(p0.x, p0.y);
            a[mt][1] = pack_h2(q0.x, q0.y);
            a[mt][2] = pack_h2(p1.x, p1.y);
            a[mt][3] = pack_h2(q1.x, q1.y);
        }
        #pragma unroll
        for (int nt = 0; nt < 4; nt++) {
            const __half* pb = sFT + (d0 + nt * 8 + r4) * PH_FT + k0 + 2 * c4;
            bf[nt][0] = *reinterpret_cast<const uint32_t*>(pb);
            bf[nt][1] = *reinterpret_cast<const uint32_t*>(pb + 8);
        }
    };
    // pipelined quad of G1 steps base..base+3
    auto g1_quad = [&](int base) {
        uint32_t a[2][2][4], bf[2][4][2];
        g1_load(base, a[0], bf[0]);
        #pragma unroll
        for (int s = 0; s < 4; s++) {
            if (s < 3) g1_load(base + s + 1, a[(s + 1) & 1], bf[(s + 1) & 1]);
            #pragma unroll
            for (int mt = 0; mt < 2; mt++)
                #pragma unroll
                for (int nt = 0; nt < 4; nt++)
                    mma_f16(acc1[mt][nt], a[s & 1][mt], bf[s & 1][nt]);
        }
    };

    // G2 fragment load for k16 step s (d-dim k); B packed from fp32 K
    auto g2_load = [&](int s, uint32_t (&a)[2][4], uint32_t (&bf)[8][2]) {
        const int k0 = s * 16;
        #pragma unroll
        for (int mt = 0; mt < 2; mt++) {
            const __half* pa = sX1 + (m0 + mt * 16 + r4) * PH_X1 + k0 + 2 * c4;
            a[mt][0] = *reinterpret_cast<const uint32_t*>(pa);
            a[mt][1] = *reinterpret_cast<const uint32_t*>(pa + 8 * PH_X1);
            a[mt][2] = *reinterpret_cast<const uint32_t*>(pa + 8);
            a[mt][3] = *reinterpret_cast<const uint32_t*>(pa + 8 * PH_X1 + 8);
        }
        #pragma unroll
        for (int nt = 0; nt < 8; nt++) {
            const int u = u0 + nt * 8 + r4;
            const float* pb = sK + (k0 + 2 * c4) * P_K + u;
            bf[nt][0] = pack_h2(pb[0],       pb[P_K]);
            bf[nt][1] = pack_h2(pb[8 * P_K], pb[9 * P_K]);
        }
    };

    // FIFO per half, per bond (entry flight = {C0,C1,K}):
    //  wait<2>|hbar| g1(0..3)   wait<1>|hbar| g1(4..7)
    //  X1 store; wait<0> (K landed); hbar; commit {C0',C1'}
    //  G2(0..3, pipelined); hbar; commit {K'}
    #pragma unroll 1
    for (int e = 0; e < BOND; e++) {
        #pragma unroll
        for (int mt = 0; mt < 2; mt++)
            #pragma unroll
            for (int nt = 0; nt < 4; nt++)
                #pragma unroll
                for (int k = 0; k < 4; k++) acc1[mt][nt][k] = 0.0f;

        cp_wait<2>(); hbar(h); g1_quad(0);
        cp_wait<1>(); hbar(h); g1_quad(4);

        // X1 -> fp16 smem (C-fragment pairs are k-adjacent: direct half2 pack)
        #pragma unroll
        for (int mt = 0; mt < 2; mt++) {
            #pragma unroll
            for (int nt = 0; nt < 4; nt++) {
                const int row = m0 + mt * 16 + r4;
                const int col = d0 + nt * 8 + 2 * c4;
                *reinterpret_cast<uint32_t*>(sX1 + row * PH_X1 + col) =
                    pack_h2(acc1[mt][nt][0], acc1[mt][nt][1]);
                *reinterpret_cast<uint32_t*>(sX1 + (row + 8) * PH_X1 + col) =
                    pack_h2(acc1[mt][nt][2], acc1[mt][nt][3]);
            }
        }
        cp_wait<0>();                           // K(e) landed
        hbar(h);                                // X1 visible; adj(e) reads closed
        if (e + 1 < BOND) commit_adj(e + 1);    // flies during G2

        {
            uint32_t a[2][2][4], bf[2][8][2];
            g2_load(0, a[0], bf[0]);
            #pragma unroll
            for (int s = 0; s < 4; s++) {
                if (s < 3) g2_load(s + 1, a[(s + 1) & 1], bf[(s + 1) & 1]);
                #pragma unroll
                for (int mt = 0; mt < 2; mt++)
                    #pragma unroll
                    for (int nt = 0; nt < 8; nt++)
                        mma_f16(acc2[mt][nt], a[s & 1][mt], bf[s & 1][nt]);
            }
        }

        hbar(h);                                // K(e) reads closed
        if (e + 1 < BOND) { stage_K(e + 1); CP_COMMIT(); }
    }

    // ---- epilogue: ReLU + store OUT[b][mh+m][u] ----
    float* ob = out + (size_t)b * (NDIM * UNITS) + (size_t)mh * UNITS;
    #pragma unroll
    for (int mt = 0; mt < 2; mt++) {
        #pragma unroll
        for (int nt = 0; nt < 8; nt++) {
            const int row = m0 + mt * 16 + r4;
            const int col = u0 + nt * 8 + 2 * c4;
            float2 v0 = make_float2(fmaxf(acc2[mt][nt][0], 0.0f), fmaxf(acc2[mt][nt][1], 0.0f));
            float2 v1 = make_float2(fmaxf(acc2[mt][nt][2], 0.0f), fmaxf(acc2[mt][nt][3], 0.0f));
            *reinterpret_cast<float2*>(ob + row * UNITS + col)       = v0;
            *reinterpret_cast<float2*>(ob + (row + 8) * UNITS + col) = v1;
        }
    }
}

extern "C" void kernel_launch(void* const* d_in, const int* in_sizes, int n_in,
                              void* d_out, int out_size) {
    const float* adj  = nullptr;
    const float* feat = nullptr;
    const float* ker  = nullptr;
    for (int i = 0; i < n_in; i++) {
        if      (in_sizes[i] == BSZ * BOND * NDIM * NDIM)  adj  = (const float*)d_in[i];
        else if (in_sizes[i] == BSZ * NDIM * ATOM)         feat = (const float*)d_in[i];
        else if (in_sizes[i] == BSZ * BOND * ATOM * UNITS) ker  = (const float*)d_in[i];
    }
    if (!adj)  adj  = (const float*)d_in[0];
    if (!feat) feat = (const float*)d_in[1];
    if (!ker)  ker  = (const float*)d_in[2];

    cudaFuncSetAttribute(rgc_kernel, cudaFuncAttributeMaxDynamicSharedMemorySize, SMEM_BYTES);
    rgc_kernel<<<BSZ, THREADS, SMEM_BYTES>>>(adj, feat, ker, (float*)d_out);
}